// round 2
// baseline (speedup 1.0000x reference)
#include <cuda_runtime.h>

#define NROWS 8192
#define DIM   512
#define HID   1024

// Scratch (allocation-free: __device__ globals), all 16B-aligned.
__device__ __align__(16) float g_part[128 * DIM];
__device__ __align__(16) float g_s[DIM];
__device__ __align__(16) float g_a1[DIM], g_c1[DIM];
__device__ __align__(16) float g_a2[DIM], g_c2[DIM];
__device__ __align__(16) float g_y[(size_t)NROWS * HID];   // 32 MB

// ---------------- stage 1: column partial sums of h ----------------
__global__ void colsum_kernel(const float* __restrict__ h) {
    int d  = threadIdx.x;            // 0..511
    int r0 = blockIdx.x * 64;        // 128 blocks x 64 rows
    float s = 0.f;
#pragma unroll 8
    for (int r = 0; r < 64; r++)
        s += h[(size_t)(r0 + r) * DIM + d];
    g_part[blockIdx.x * DIM + d] = s;
}

// ---------------- stage 2: s = colsum(h)@vw + N*vb ----------------
__global__ void prep1_kernel(const float* __restrict__ vw,
                             const float* __restrict__ vb) {
    __shared__ float hs[DIM];
    for (int i = threadIdx.x; i < DIM; i += blockDim.x) {
        float s = 0.f;
#pragma unroll 8
        for (int b = 0; b < 128; b++) s += g_part[b * DIM + i];
        hs[i] = s;
    }
    __syncthreads();
    int d = blockIdx.x * blockDim.x + threadIdx.x;   // 2 blocks x 256
    float s = 0.f;
#pragma unroll 8
    for (int k = 0; k < DIM; k++) s = fmaf(hs[k], vw[k * DIM + d], s);
    g_s[d] = s + 8192.0f * vb[d];
}

// ---------------- stage 3: t = s@ow+ob; fold bn affines ----------------
__global__ void prep2_kernel(const float* __restrict__ ow, const float* __restrict__ ob,
                             const float* __restrict__ g1, const float* __restrict__ b1,
                             const float* __restrict__ m1, const float* __restrict__ v1,
                             const float* __restrict__ g2, const float* __restrict__ b2,
                             const float* __restrict__ m2, const float* __restrict__ v2) {
    __shared__ float ss[DIM];
    for (int i = threadIdx.x; i < DIM; i += blockDim.x) ss[i] = g_s[i];
    __syncthreads();
    int d = blockIdx.x * blockDim.x + threadIdx.x;   // 2 blocks x 256
    float t = 0.f;
#pragma unroll 8
    for (int k = 0; k < DIM; k++) t = fmaf(ss[k], ow[k * DIM + d], t);
    t += ob[d];
    float A1 = g1[d] * rsqrtf(v1[d] + 1e-5f);
    g_a1[d] = A1;
    g_c1[d] = (t - m1[d]) * A1 + b1[d];
    float A2 = g2[d] * rsqrtf(v2[d] + 1e-5f);
    g_a2[d] = A2;
    g_c2[d] = b2[d] - m2[d] * A2;
}

// ---------------- FFN GEMM 1: y = relu((h*a1+c1) @ f1w + f1b) ----------------
// M=8192, K=512, N=1024. BM=BN=128, BK=16, 256 threads, 8x8 microtile.
__global__ __launch_bounds__(256) void ffn1_kernel(
    const float* __restrict__ h, const float* __restrict__ w,
    const float* __restrict__ bias) {
    __shared__ __align__(16) float As[16][132];   // transposed, padded
    __shared__ __align__(16) float Bs[16][128];
    const int bm = blockIdx.y * 128;
    const int bn = blockIdx.x * 128;
    const int tid = threadIdx.x;
    const int tx = tid & 15, ty = tid >> 4;

    float acc[8][8];
#pragma unroll
    for (int m = 0; m < 8; m++)
#pragma unroll
        for (int n = 0; n < 8; n++) acc[m][n] = 0.f;

    for (int k0 = 0; k0 < DIM; k0 += 16) {
        // A tile: fold bn1 affine while staging (transposed to [k][m])
#pragma unroll
        for (int i = 0; i < 2; i++) {
            int fidx = tid + i * 256;          // 512 float4 slots
            int row  = fidx >> 2;              // 0..127
            int c4   = (fidx & 3) << 2;        // 0,4,8,12
            float4 hv = *(const float4*)(h + (size_t)(bm + row) * DIM + k0 + c4);
            float4 av = *(const float4*)(g_a1 + k0 + c4);
            float4 cv = *(const float4*)(g_c1 + k0 + c4);
            As[c4 + 0][row] = fmaf(hv.x, av.x, cv.x);
            As[c4 + 1][row] = fmaf(hv.y, av.y, cv.y);
            As[c4 + 2][row] = fmaf(hv.z, av.z, cv.z);
            As[c4 + 3][row] = fmaf(hv.w, av.w, cv.w);
        }
        // B tile [k][n]
#pragma unroll
        for (int i = 0; i < 2; i++) {
            int fidx = tid + i * 256;
            int kk = fidx >> 5;
            int j4 = (fidx & 31) << 2;
            *(float4*)&Bs[kk][j4] =
                *(const float4*)(w + (size_t)(k0 + kk) * HID + bn + j4);
        }
        __syncthreads();
#pragma unroll
        for (int kk = 0; kk < 16; kk++) {
            float4 a0 = *(const float4*)&As[kk][ty * 8];
            float4 a1 = *(const float4*)&As[kk][ty * 8 + 4];
            float4 b0 = *(const float4*)&Bs[kk][tx * 8];
            float4 b1 = *(const float4*)&Bs[kk][tx * 8 + 4];
            float am[8] = {a0.x, a0.y, a0.z, a0.w, a1.x, a1.y, a1.z, a1.w};
            float bn_[8] = {b0.x, b0.y, b0.z, b0.w, b1.x, b1.y, b1.z, b1.w};
#pragma unroll
            for (int m = 0; m < 8; m++)
#pragma unroll
                for (int n = 0; n < 8; n++)
                    acc[m][n] = fmaf(am[m], bn_[n], acc[m][n]);
        }
        __syncthreads();
    }
    const int row0 = bm + ty * 8;
    const int col0 = bn + tx * 8;
    float4 bv0 = *(const float4*)(bias + col0);
    float4 bv1 = *(const float4*)(bias + col0 + 4);
#pragma unroll
    for (int m = 0; m < 8; m++) {
        float4 o0 = make_float4(fmaxf(acc[m][0] + bv0.x, 0.f),
                                fmaxf(acc[m][1] + bv0.y, 0.f),
                                fmaxf(acc[m][2] + bv0.z, 0.f),
                                fmaxf(acc[m][3] + bv0.w, 0.f));
        float4 o1 = make_float4(fmaxf(acc[m][4] + bv1.x, 0.f),
                                fmaxf(acc[m][5] + bv1.y, 0.f),
                                fmaxf(acc[m][6] + bv1.z, 0.f),
                                fmaxf(acc[m][7] + bv1.w, 0.f));
        float* yr = g_y + (size_t)(row0 + m) * HID + col0;
        *(float4*)yr = o0;
        *(float4*)(yr + 4) = o1;
    }
}

// ---------------- FFN GEMM 2 + residual + bn2 ----------------
// out = ((h*a1+c1) + y@f2w + f2b) * a2 + c2
// M=8192, K=1024, N=512. BM=BN=128, BK=16, 256 threads, 8x8 microtile.
__global__ __launch_bounds__(256) void ffn2_kernel(
    const float* __restrict__ h, const float* __restrict__ w,
    const float* __restrict__ bias, float* __restrict__ out) {
    __shared__ __align__(16) float As[16][132];
    __shared__ __align__(16) float Bs[16][128];
    const int bm = blockIdx.y * 128;
    const int bn = blockIdx.x * 128;
    const int tid = threadIdx.x;
    const int tx = tid & 15, ty = tid >> 4;

    float acc[8][8];
#pragma unroll
    for (int m = 0; m < 8; m++)
#pragma unroll
        for (int n = 0; n < 8; n++) acc[m][n] = 0.f;

    for (int k0 = 0; k0 < HID; k0 += 16) {
#pragma unroll
        for (int i = 0; i < 2; i++) {
            int fidx = tid + i * 256;
            int row  = fidx >> 2;
            int c4   = (fidx & 3) << 2;
            float4 yv = *(const float4*)(g_y + (size_t)(bm + row) * HID + k0 + c4);
            As[c4 + 0][row] = yv.x;
            As[c4 + 1][row] = yv.y;
            As[c4 + 2][row] = yv.z;
            As[c4 + 3][row] = yv.w;
        }
#pragma unroll
        for (int i = 0; i < 2; i++) {
            int fidx = tid + i * 256;
            int kk = fidx >> 5;
            int j4 = (fidx & 31) << 2;
            *(float4*)&Bs[kk][j4] =
                *(const float4*)(w + (size_t)(k0 + kk) * DIM + bn + j4);
        }
        __syncthreads();
#pragma unroll
        for (int kk = 0; kk < 16; kk++) {
            float4 a0 = *(const float4*)&As[kk][ty * 8];
            float4 a1 = *(const float4*)&As[kk][ty * 8 + 4];
            float4 b0 = *(const float4*)&Bs[kk][tx * 8];
            float4 b1 = *(const float4*)&Bs[kk][tx * 8 + 4];
            float am[8] = {a0.x, a0.y, a0.z, a0.w, a1.x, a1.y, a1.z, a1.w};
            float bn_[8] = {b0.x, b0.y, b0.z, b0.w, b1.x, b1.y, b1.z, b1.w};
#pragma unroll
            for (int m = 0; m < 8; m++)
#pragma unroll
                for (int n = 0; n < 8; n++)
                    acc[m][n] = fmaf(am[m], bn_[n], acc[m][n]);
        }
        __syncthreads();
    }
    const int row0 = bm + ty * 8;
    const int col0 = bn + tx * 8;
    float4 fb0 = *(const float4*)(bias + col0);
    float4 fb1 = *(const float4*)(bias + col0 + 4);
    float4 a10 = *(const float4*)(g_a1 + col0);
    float4 a11 = *(const float4*)(g_a1 + col0 + 4);
    float4 c10 = *(const float4*)(g_c1 + col0);
    float4 c11 = *(const float4*)(g_c1 + col0 + 4);
    float4 a20 = *(const float4*)(g_a2 + col0);
    float4 a21 = *(const float4*)(g_a2 + col0 + 4);
    float4 c20 = *(const float4*)(g_c2 + col0);
    float4 c21 = *(const float4*)(g_c2 + col0 + 4);
#pragma unroll
    for (int m = 0; m < 8; m++) {
        int row = row0 + m;
        const float* hr = h + (size_t)row * DIM + col0;
        float4 h0 = *(const float4*)hr;
        float4 h1 = *(const float4*)(hr + 4);
        float4 o0, o1;
        o0.x = (fmaf(h0.x, a10.x, c10.x) + acc[m][0] + fb0.x) * a20.x + c20.x;
        o0.y = (fmaf(h0.y, a10.y, c10.y) + acc[m][1] + fb0.y) * a20.y + c20.y;
        o0.z = (fmaf(h0.z, a10.z, c10.z) + acc[m][2] + fb0.z) * a20.z + c20.z;
        o0.w = (fmaf(h0.w, a10.w, c10.w) + acc[m][3] + fb0.w) * a20.w + c20.w;
        o1.x = (fmaf(h1.x, a11.x, c11.x) + acc[m][4] + fb1.x) * a21.x + c21.x;
        o1.y = (fmaf(h1.y, a11.y, c11.y) + acc[m][5] + fb1.y) * a21.y + c21.y;
        o1.z = (fmaf(h1.z, a11.z, c11.z) + acc[m][6] + fb1.z) * a21.z + c21.z;
        o1.w = (fmaf(h1.w, a11.w, c11.w) + acc[m][7] + fb1.w) * a21.w + c21.w;
        float* orow = out + (size_t)row * DIM + col0;
        *(float4*)orow = o0;
        *(float4*)(orow + 4) = o1;
    }
}

extern "C" void kernel_launch(void* const* d_in, const int* in_sizes, int n_in,
                              void* d_out, int out_size) {
    // metadata order: A,h,qw,qb,kw,kb,vw,vb,ow,ob,f1w,f1b,f2w,f2b,bn1_*,bn2_*
    const float* h   = (const float*)d_in[1];
    const float* vw  = (const float*)d_in[6];
    const float* vb  = (const float*)d_in[7];
    const float* ow  = (const float*)d_in[8];
    const float* ob  = (const float*)d_in[9];
    const float* f1w = (const float*)d_in[10];
    const float* f1b = (const float*)d_in[11];
    const float* f2w = (const float*)d_in[12];
    const float* f2b = (const float*)d_in[13];
    const float* b1g = (const float*)d_in[14];
    const float* b1b = (const float*)d_in[15];
    const float* b1m = (const float*)d_in[16];
    const float* b1v = (const float*)d_in[17];
    const float* b2g = (const float*)d_in[18];
    const float* b2b = (const float*)d_in[19];
    const float* b2m = (const float*)d_in[20];
    const float* b2v = (const float*)d_in[21];
    float* out = (float*)d_out;

    colsum_kernel<<<128, 512>>>(h);
    prep1_kernel<<<2, 256>>>(vw, vb);
    prep2_kernel<<<2, 256>>>(ow, ob, b1g, b1b, b1m, b1v, b2g, b2b, b2m, b2v);
    dim3 g1(HID / 128, NROWS / 128);   // (8, 64)
    ffn1_kernel<<<g1, 256>>>(h, f1w, f1b);
    dim3 g2(DIM / 128, NROWS / 128);   // (4, 64)
    ffn2_kernel<<<g2, 256>>>(h, f2w, f2b, out);
}

// round 3
// speedup vs baseline: 2.1957x; 2.1957x over previous
#include <cuda_runtime.h>

#define NROWS 8192
#define DIM   512
#define HID   1024

// Scratch (allocation-free: __device__ globals), all 16B-aligned.
__device__ __align__(16) float g_part[128 * DIM];
__device__ __align__(16) float g_s[DIM];
__device__ __align__(16) float g_a1[DIM], g_c1[DIM];
__device__ __align__(16) float g_a2[DIM], g_c2[DIM];
__device__ __align__(16) float g_y[(size_t)NROWS * HID];   // 32 MB

// ---------------- tf32 + mma helpers ----------------
__device__ __forceinline__ unsigned tf32r(float x) {
    unsigned r;
    asm("cvt.rna.tf32.f32 %0, %1;" : "=r"(r) : "f"(x));
    return r;
}
__device__ __forceinline__ void mma_tf32(float* d, const unsigned* a, const unsigned* b) {
    asm volatile(
        "mma.sync.aligned.m16n8k8.row.col.f32.tf32.tf32.f32 "
        "{%0,%1,%2,%3}, {%4,%5,%6,%7}, {%8,%9}, {%0,%1,%2,%3};"
        : "+f"(d[0]), "+f"(d[1]), "+f"(d[2]), "+f"(d[3])
        : "r"(a[0]), "r"(a[1]), "r"(a[2]), "r"(a[3]), "r"(b[0]), "r"(b[1]));
}

// ---------------- stage 1: column partial sums of h ----------------
__global__ void colsum_kernel(const float* __restrict__ h) {
    int d  = threadIdx.x;
    int r0 = blockIdx.x * 64;
    float s = 0.f;
#pragma unroll 8
    for (int r = 0; r < 64; r++)
        s += h[(size_t)(r0 + r) * DIM + d];
    g_part[blockIdx.x * DIM + d] = s;
}

// ---------------- stage 2: s = colsum(h)@vw + N*vb ----------------
__global__ void prep1_kernel(const float* __restrict__ vw,
                             const float* __restrict__ vb) {
    __shared__ float hs[DIM];
    for (int i = threadIdx.x; i < DIM; i += blockDim.x) {
        float s = 0.f;
#pragma unroll 8
        for (int b = 0; b < 128; b++) s += g_part[b * DIM + i];
        hs[i] = s;
    }
    __syncthreads();
    int d = blockIdx.x * blockDim.x + threadIdx.x;
    float s = 0.f;
#pragma unroll 8
    for (int k = 0; k < DIM; k++) s = fmaf(hs[k], vw[k * DIM + d], s);
    g_s[d] = s + 8192.0f * vb[d];
}

// ---------------- stage 3: t = s@ow+ob; fold bn affines ----------------
__global__ void prep2_kernel(const float* __restrict__ ow, const float* __restrict__ ob,
                             const float* __restrict__ g1, const float* __restrict__ b1,
                             const float* __restrict__ m1, const float* __restrict__ v1,
                             const float* __restrict__ g2, const float* __restrict__ b2,
                             const float* __restrict__ m2, const float* __restrict__ v2) {
    __shared__ float ss[DIM];
    for (int i = threadIdx.x; i < DIM; i += blockDim.x) ss[i] = g_s[i];
    __syncthreads();
    int d = blockIdx.x * blockDim.x + threadIdx.x;
    float t = 0.f;
#pragma unroll 8
    for (int k = 0; k < DIM; k++) t = fmaf(ss[k], ow[k * DIM + d], t);
    t += ob[d];
    float A1 = g1[d] * rsqrtf(v1[d] + 1e-5f);
    g_a1[d] = A1;
    g_c1[d] = (t - m1[d]) * A1 + b1[d];
    float A2 = g2[d] * rsqrtf(v2[d] + 1e-5f);
    g_a2[d] = A2;
    g_c2[d] = b2[d] - m2[d] * A2;
}

// =====================================================================
// tf32 MMA GEMM 1: y = relu((h*a1+c1) @ f1w + f1b)
// M=8192, K=512, N=1024. Block 128x128, BK=32, 8 warps, warp = 32x64.
// SMEM staged in fragment order:
//   As[kstep(4)][mtile(8)][lane(32)][j(4)]  (u32, tf32 bits)
//   Bs[kstep(4)][ntile(16)][lane(32)][j(2)]
// lane rotation: A rot=kstep, B rot=ntile (write+read both rotated).
// =====================================================================
__global__ __launch_bounds__(256, 2) void ffn1_kernel(
    const float* __restrict__ h, const float* __restrict__ w,
    const float* __restrict__ bias) {
    __shared__ __align__(16) unsigned As[4096];
    __shared__ __align__(16) unsigned Bs[4096];
    const int bm = blockIdx.y * 128;
    const int bn = blockIdx.x * 128;
    const int tid = threadIdx.x;
    const int lane = tid & 31, wid = tid >> 5;
    const int w_m = wid & 3, w_n = wid >> 2;      // 4 x 2 warp grid
    const int g = lane >> 2, tg = lane & 3;

    float acc[2][8][4];
#pragma unroll
    for (int mt = 0; mt < 2; mt++)
#pragma unroll
        for (int nt = 0; nt < 8; nt++)
#pragma unroll
            for (int q = 0; q < 4; q++) acc[mt][nt][q] = 0.f;

    for (int k0 = 0; k0 < DIM; k0 += 32) {
        // ---- stage A (fold bn1 affine, cvt tf32) ----
#pragma unroll
        for (int i = 0; i < 4; i++) {
            int fidx = tid + i * 256;          // 1024 float4 slots
            int row = fidx >> 3;               // 0..127
            int c4  = (fidx & 7) << 2;         // 0..28
            float4 hv = *(const float4*)(h + (size_t)(bm + row) * DIM + k0 + c4);
            float4 av = *(const float4*)(g_a1 + k0 + c4);
            float4 cv = *(const float4*)(g_c1 + k0 + c4);
            float vals[4] = {fmaf(hv.x, av.x, cv.x), fmaf(hv.y, av.y, cv.y),
                             fmaf(hv.z, av.z, cv.z), fmaf(hv.w, av.w, cv.w)};
            int mtile = row >> 4;
            int lane_r = (row & 7) << 2;
            int jb0 = (row >> 3) & 1;
#pragma unroll
            for (int jj = 0; jj < 4; jj++) {
                int cc = c4 + jj;
                int kstep = cc >> 3;
                int l = lane_r | (cc & 3);
                int phys = (l + kstep) & 31;
                int j = (((cc >> 2) & 1) << 1) | jb0;
                As[((kstep << 3) + mtile) * 128 + phys * 4 + j] = tf32r(vals[jj]);
            }
        }
        // ---- stage B ----
#pragma unroll
        for (int i = 0; i < 4; i++) {
            int fidx = tid + i * 256;
            int k  = fidx >> 5;                // 0..31
            int n4 = (fidx & 31) << 2;         // 0..124
            float4 wv = *(const float4*)(w + (size_t)(k0 + k) * HID + bn + n4);
            float vals[4] = {wv.x, wv.y, wv.z, wv.w};
            int kstep = k >> 3;
            int j = (k >> 2) & 1;
            int k3 = k & 3;
#pragma unroll
            for (int jj = 0; jj < 4; jj++) {
                int n = n4 + jj;
                int ntile = n >> 3;
                int l = ((n & 7) << 2) | k3;
                int phys = (l + ntile) & 31;
                Bs[((kstep << 4) + ntile) * 64 + phys * 2 + j] = tf32r(vals[jj]);
            }
        }
        __syncthreads();
        // ---- compute ----
#pragma unroll
        for (int ks = 0; ks < 4; ks++) {
            unsigned afr[2][4], bfr[8][2];
            int physa = (lane + ks) & 31;
#pragma unroll
            for (int mt = 0; mt < 2; mt++) {
                int mtile = w_m * 2 + mt;
                uint4 v = *(const uint4*)&As[((ks << 3) + mtile) * 128 + physa * 4];
                afr[mt][0] = v.x; afr[mt][1] = v.y; afr[mt][2] = v.z; afr[mt][3] = v.w;
            }
#pragma unroll
            for (int nt = 0; nt < 8; nt++) {
                int ntile = w_n * 8 + nt;
                int physb = (lane + ntile) & 31;
                uint2 v = *(const uint2*)&Bs[((ks << 4) + ntile) * 64 + physb * 2];
                bfr[nt][0] = v.x; bfr[nt][1] = v.y;
            }
#pragma unroll
            for (int mt = 0; mt < 2; mt++)
#pragma unroll
                for (int nt = 0; nt < 8; nt++)
                    mma_tf32(acc[mt][nt], afr[mt], bfr[nt]);
        }
        __syncthreads();
    }
    // ---- epilogue: bias + relu -> g_y ----
#pragma unroll
    for (int nt = 0; nt < 8; nt++) {
        int col = bn + w_n * 64 + nt * 8 + 2 * tg;
        float2 bv = *(const float2*)(bias + col);
#pragma unroll
        for (int mt = 0; mt < 2; mt++) {
            int r0 = bm + w_m * 32 + mt * 16 + g;
            float2 o0 = make_float2(fmaxf(acc[mt][nt][0] + bv.x, 0.f),
                                    fmaxf(acc[mt][nt][1] + bv.y, 0.f));
            float2 o1 = make_float2(fmaxf(acc[mt][nt][2] + bv.x, 0.f),
                                    fmaxf(acc[mt][nt][3] + bv.y, 0.f));
            *(float2*)(g_y + (size_t)r0 * HID + col) = o0;
            *(float2*)(g_y + (size_t)(r0 + 8) * HID + col) = o1;
        }
    }
}

// =====================================================================
// tf32 MMA GEMM 2 + residual + bn2:
// out = ((h*a1+c1) + y@f2w + f2b) * a2 + c2
// M=8192, K=1024, N=512. Same tiling.
// =====================================================================
__global__ __launch_bounds__(256, 2) void ffn2_kernel(
    const float* __restrict__ h, const float* __restrict__ w,
    const float* __restrict__ bias, float* __restrict__ out) {
    __shared__ __align__(16) unsigned As[4096];
    __shared__ __align__(16) unsigned Bs[4096];
    const int bm = blockIdx.y * 128;
    const int bn = blockIdx.x * 128;
    const int tid = threadIdx.x;
    const int lane = tid & 31, wid = tid >> 5;
    const int w_m = wid & 3, w_n = wid >> 2;
    const int g = lane >> 2, tg = lane & 3;

    float acc[2][8][4];
#pragma unroll
    for (int mt = 0; mt < 2; mt++)
#pragma unroll
        for (int nt = 0; nt < 8; nt++)
#pragma unroll
            for (int q = 0; q < 4; q++) acc[mt][nt][q] = 0.f;

    for (int k0 = 0; k0 < HID; k0 += 32) {
        // ---- stage A from g_y ----
#pragma unroll
        for (int i = 0; i < 4; i++) {
            int fidx = tid + i * 256;
            int row = fidx >> 3;
            int c4  = (fidx & 7) << 2;
            float4 yv = *(const float4*)(g_y + (size_t)(bm + row) * HID + k0 + c4);
            float vals[4] = {yv.x, yv.y, yv.z, yv.w};
            int mtile = row >> 4;
            int lane_r = (row & 7) << 2;
            int jb0 = (row >> 3) & 1;
#pragma unroll
            for (int jj = 0; jj < 4; jj++) {
                int cc = c4 + jj;
                int kstep = cc >> 3;
                int l = lane_r | (cc & 3);
                int phys = (l + kstep) & 31;
                int j = (((cc >> 2) & 1) << 1) | jb0;
                As[((kstep << 3) + mtile) * 128 + phys * 4 + j] = tf32r(vals[jj]);
            }
        }
        // ---- stage B ----
#pragma unroll
        for (int i = 0; i < 4; i++) {
            int fidx = tid + i * 256;
            int k  = fidx >> 5;
            int n4 = (fidx & 31) << 2;
            float4 wv = *(const float4*)(w + (size_t)(k0 + k) * DIM + bn + n4);
            float vals[4] = {wv.x, wv.y, wv.z, wv.w};
            int kstep = k >> 3;
            int j = (k >> 2) & 1;
            int k3 = k & 3;
#pragma unroll
            for (int jj = 0; jj < 4; jj++) {
                int n = n4 + jj;
                int ntile = n >> 3;
                int l = ((n & 7) << 2) | k3;
                int phys = (l + ntile) & 31;
                Bs[((kstep << 4) + ntile) * 64 + phys * 2 + j] = tf32r(vals[jj]);
            }
        }
        __syncthreads();
#pragma unroll
        for (int ks = 0; ks < 4; ks++) {
            unsigned afr[2][4], bfr[8][2];
            int physa = (lane + ks) & 31;
#pragma unroll
            for (int mt = 0; mt < 2; mt++) {
                int mtile = w_m * 2 + mt;
                uint4 v = *(const uint4*)&As[((ks << 3) + mtile) * 128 + physa * 4];
                afr[mt][0] = v.x; afr[mt][1] = v.y; afr[mt][2] = v.z; afr[mt][3] = v.w;
            }
#pragma unroll
            for (int nt = 0; nt < 8; nt++) {
                int ntile = w_n * 8 + nt;
                int physb = (lane + ntile) & 31;
                uint2 v = *(const uint2*)&Bs[((ks << 4) + ntile) * 64 + physb * 2];
                bfr[nt][0] = v.x; bfr[nt][1] = v.y;
            }
#pragma unroll
            for (int mt = 0; mt < 2; mt++)
#pragma unroll
                for (int nt = 0; nt < 8; nt++)
                    mma_tf32(acc[mt][nt], afr[mt], bfr[nt]);
        }
        __syncthreads();
    }
    // ---- epilogue: residual (bn1-folded h) + f2b, then bn2 affine ----
#pragma unroll
    for (int nt = 0; nt < 8; nt++) {
        int col = bn + w_n * 64 + nt * 8 + 2 * tg;
        float2 fbv = *(const float2*)(bias + col);
        float2 a1v = *(const float2*)(g_a1 + col);
        float2 c1v = *(const float2*)(g_c1 + col);
        float2 a2v = *(const float2*)(g_a2 + col);
        float2 c2v = *(const float2*)(g_c2 + col);
#pragma unroll
        for (int mt = 0; mt < 2; mt++) {
            int r0 = bm + w_m * 32 + mt * 16 + g;
            float2 h0 = *(const float2*)(h + (size_t)r0 * DIM + col);
            float2 h1 = *(const float2*)(h + (size_t)(r0 + 8) * DIM + col);
            float2 o0, o1;
            o0.x = (fmaf(h0.x, a1v.x, c1v.x) + acc[mt][nt][0] + fbv.x) * a2v.x + c2v.x;
            o0.y = (fmaf(h0.y, a1v.y, c1v.y) + acc[mt][nt][1] + fbv.y) * a2v.y + c2v.y;
            o1.x = (fmaf(h1.x, a1v.x, c1v.x) + acc[mt][nt][2] + fbv.x) * a2v.x + c2v.x;
            o1.y = (fmaf(h1.y, a1v.y, c1v.y) + acc[mt][nt][3] + fbv.y) * a2v.y + c2v.y;
            *(float2*)(out + (size_t)r0 * DIM + col) = o0;
            *(float2*)(out + (size_t)(r0 + 8) * DIM + col) = o1;
        }
    }
}

extern "C" void kernel_launch(void* const* d_in, const int* in_sizes, int n_in,
                              void* d_out, int out_size) {
    // metadata order: A,h,qw,qb,kw,kb,vw,vb,ow,ob,f1w,f1b,f2w,f2b,bn1_*,bn2_*
    const float* h   = (const float*)d_in[1];
    const float* vw  = (const float*)d_in[6];
    const float* vb  = (const float*)d_in[7];
    const float* ow  = (const float*)d_in[8];
    const float* ob  = (const float*)d_in[9];
    const float* f1w = (const float*)d_in[10];
    const float* f1b = (const float*)d_in[11];
    const float* f2w = (const float*)d_in[12];
    const float* f2b = (const float*)d_in[13];
    const float* b1g = (const float*)d_in[14];
    const float* b1b = (const float*)d_in[15];
    const float* b1m = (const float*)d_in[16];
    const float* b1v = (const float*)d_in[17];
    const float* b2g = (const float*)d_in[18];
    const float* b2b = (const float*)d_in[19];
    const float* b2m = (const float*)d_in[20];
    const float* b2v = (const float*)d_in[21];
    float* out = (float*)d_out;

    colsum_kernel<<<128, 512>>>(h);
    prep1_kernel<<<2, 256>>>(vw, vb);
    prep2_kernel<<<2, 256>>>(ow, ob, b1g, b1b, b1m, b1v, b2g, b2b, b2m, b2v);
    dim3 g1(HID / 128, NROWS / 128);   // (8, 64)
    ffn1_kernel<<<g1, 256>>>(h, f1w, f1b);
    dim3 g2(DIM / 128, NROWS / 128);   // (4, 64)
    ffn2_kernel<<<g2, 256>>>(h, f2w, f2b, out);
}